// round 6
// baseline (speedup 1.0000x reference)
#include <cuda_runtime.h>
#include <math.h>

#define SAC_WARMUP 365
#define PF 4

typedef unsigned long long u64;

// ---- Blackwell packed-fp32 (f32x2) primitives: one instruction, two basins ----
__device__ __forceinline__ u64 pk(float a, float b) {
    u64 r; asm("mov.b64 %0, {%1, %2};" : "=l"(r)
               : "r"(__float_as_uint(a)), "r"(__float_as_uint(b)));
    return r;
}
__device__ __forceinline__ void up(u64 p, float& a, float& b) {
    unsigned x, y; asm("mov.b64 {%0, %1}, %2;" : "=r"(x), "=r"(y) : "l"(p));
    a = __uint_as_float(x); b = __uint_as_float(y);
}
__device__ __forceinline__ u64 add2(u64 a, u64 b) {
    u64 r; asm("add.rn.f32x2 %0, %1, %2;" : "=l"(r) : "l"(a), "l"(b)); return r;
}
__device__ __forceinline__ u64 mul2(u64 a, u64 b) {
    u64 r; asm("mul.rn.f32x2 %0, %1, %2;" : "=l"(r) : "l"(a), "l"(b)); return r;
}
__device__ __forceinline__ u64 fma2(u64 a, u64 b, u64 c) {
    u64 r; asm("fma.rn.f32x2 %0, %1, %2, %3;" : "=l"(r) : "l"(a), "l"(b), "l"(c)); return r;
}
// clamps: no min/max.f32x2 — scalar FMNMX on the halves (pack/unpack is reg aliasing)
__device__ __forceinline__ u64 min2(u64 x, u64 y) {
    float a,b,c,d; up(x,a,b); up(y,c,d);
    return pk(fminf(a,c), fminf(b,d));
}
__device__ __forceinline__ u64 max2(u64 x, u64 y) {
    float a,b,c,d; up(x,a,b); up(y,c,d);
    return pk(fmaxf(a,c), fmaxf(b,d));
}
__device__ __forceinline__ u64 relu2(u64 x) {
    float a,b; up(x,a,b);
    return pk(fmaxf(a,0.f), fmaxf(b,0.f));
}
// fmax(fmin(m, x), 0)
__device__ __forceinline__ u64 clamp0m(u64 m, u64 x) {
    float a,b,c,d; up(m,a,b); up(x,c,d);
    return pk(fmaxf(fminf(a,c),0.f), fmaxf(fminf(b,d),0.f));
}
// x^r per lane via MUFU lg2/ex2 (lg2(0)=-inf -> ex2(-inf)=0, matching 0^r for r>=1)
__device__ __forceinline__ u64 pow2x(u64 x, float ra, float rb) {
    float a,b; up(x,a,b);
    float la,lb,ea,eb;
    asm("lg2.approx.f32 %0, %1;" : "=f"(la) : "f"(a));
    asm("lg2.approx.f32 %0, %1;" : "=f"(lb) : "f"(b));
    la *= ra; lb *= rb;
    asm("ex2.approx.f32 %0, %1;" : "=f"(ea) : "f"(la));
    asm("ex2.approx.f32 %0, %1;" : "=f"(eb) : "f"(lb));
    return pk(ea, eb);
}
// reciprocal: rcp.approx + 1 Newton step per lane (off the carry-critical path)
__device__ __forceinline__ u64 rcp2(u64 x) {
    float a,b; up(x,a,b);
    float ra,rb;
    asm("rcp.approx.f32 %0, %1;" : "=f"(ra) : "f"(a));
    asm("rcp.approx.f32 %0, %1;" : "=f"(rb) : "f"(b));
    ra = ra * (2.0f - a*ra);
    rb = rb * (2.0f - b*rb);
    return pk(ra, rb);
}

// per-lane scaled constants
struct CstS {
    float kc,pctim,adimp,uztwm,lztwm,lzfsm,lzfpm,pfree,riva,rexp,uzk,lzsk,lzpk,ci,cgs,cgp;
    float r_uztwm,r_lztwm,r_ulz,r_lzfsm,r_lzfpm,sfm,lzsum,uzfwm,r_lzsum,uzsum,parea,fp2,pbu,pbuz;
    float ci1,cgs1,cgp1,c1,c2,c3;
};

__device__ __forceinline__ void load_lane(const float* __restrict__ params, int b, CstS& c) {
    const float lo[21] = {0.1f, 0.0f, 0.0f, 10.0f, 10.0f, 50.0f, 10.0f, 50.0f,
                          0.0f, 0.0f, 0.0f, 5.0f, 1.0f, 0.1f, 0.01f, 0.001f,
                          0.5f, 0.95f, 0.98f, 0.0f, 0.0f};
    const float hi[21] = {1.2f, 0.1f, 0.3f, 100.0f, 100.0f, 400.0f, 100.0f, 1000.0f,
                          0.3f, 0.5f, 0.1f, 350.0f, 4.0f, 0.5f, 0.35f, 0.05f,
                          0.9f, 0.998f, 0.998f, 1.0f, 0.5f};
    float pr[21];
#pragma unroll
    for (int i = 0; i < 21; i++)
        pr[i] = lo[i] + params[(size_t)b * 21 + i] * (hi[i] - lo[i]);

    c.kc = pr[0]; c.pctim = pr[1]; c.adimp = pr[2];
    c.uztwm = pr[3]; c.uzfwm = pr[4]; c.lztwm = pr[5];
    c.lzfsm = pr[6]; c.lzfpm = pr[7];
    c.pfree = pr[9]; c.riva = pr[10];
    float zperc = pr[11];
    c.rexp = pr[12]; c.uzk = pr[13];
    c.lzsk = pr[14]; c.lzpk = pr[15];
    c.ci = pr[16]; c.cgs = pr[17]; c.cgp = pr[18];
    float ke = pr[19], xe = pr[20];

    c.r_uztwm = 1.0f / c.uztwm;
    c.r_lztwm = 1.0f / c.lztwm;
    c.r_ulz   = 1.0f / (c.uztwm + c.lztwm);
    c.r_lzfsm = 1.0f / c.lzfsm;
    c.r_lzfpm = 1.0f / c.lzfpm;
    c.sfm     = c.lzfsm + c.lzfpm;
    c.lzsum   = c.sfm + c.lztwm;
    c.r_lzsum = 1.0f / c.lzsum;
    c.uzsum   = c.uztwm + c.uzfwm;
    float pbase = c.lzfsm * c.lzsk + c.lzfpm * c.lzpk;
    c.parea   = 1.0f - c.pctim - c.adimp;
    c.fp2     = 2.0f * (c.lzfpm / c.sfm);
    c.pbu     = pbase / c.uzfwm;
    c.pbuz    = c.pbu * zperc;
    c.ci1     = (1.0f - c.ci)  * c.parea;
    c.cgs1    = (1.0f - c.cgs) * c.parea;
    c.cgp1    = (1.0f - c.cgp) * c.parea;
    const float dt = 0.5f;
    float mden = ke * (1.0f - xe) + dt;
    c.c1 = (ke * xe + dt) / mden;
    c.c2 = (dt - ke * xe) / mden;
    c.c3 = (ke * (1.0f - xe) - dt) / mden;
}

__global__ __launch_bounds__(128, 1)
void sac4dpl_pk(const float* __restrict__ p_and_e,   // [T, B, 2]
                const float* __restrict__ params,    // [B, 21]
                float* __restrict__ out,             // [2, T-WARMUP, B]
                int T, int B)
{
    int tb = blockIdx.x * 128 + threadIdx.x;   // basin-pair index
    int B2 = B >> 1;
    if (tb >= B2) return;

    CstS A, Bc;
    load_lane(params, tb * 2,     A);
    load_lane(params, tb * 2 + 1, Bc);

    // packed constants
    const u64 kN1     = pk(-1.0f, -1.0f);
    const u64 kOne    = pk(1.0f, 1.0f);
#define S2(a_, b_) fma2((b_), kN1, (a_))   /* a - b, exact */
    const u64 kKc     = pk(A.kc, Bc.kc);
    const u64 kPctim  = pk(A.pctim, Bc.pctim);
    const u64 kAdimp  = pk(A.adimp, Bc.adimp);
    const u64 kUztwm  = pk(A.uztwm, Bc.uztwm);
    const u64 kLztwm  = pk(A.lztwm, Bc.lztwm);
    const u64 kLzfsm  = pk(A.lzfsm, Bc.lzfsm);
    const u64 kLzfpm  = pk(A.lzfpm, Bc.lzfpm);
    const u64 kPfree  = pk(A.pfree, Bc.pfree);
    const u64 kRiva   = pk(A.riva, Bc.riva);
    const u64 kUzk    = pk(A.uzk, Bc.uzk);
    const u64 kLzsk   = pk(A.lzsk, Bc.lzsk);
    const u64 kLzpk   = pk(A.lzpk, Bc.lzpk);
    const u64 kCi     = pk(A.ci, Bc.ci);
    const u64 kCgs    = pk(A.cgs, Bc.cgs);
    const u64 kCgp    = pk(A.cgp, Bc.cgp);
    const u64 kRuztwm = pk(A.r_uztwm, Bc.r_uztwm);
    const u64 kRlztwm = pk(A.r_lztwm, Bc.r_lztwm);
    const u64 kRulz   = pk(A.r_ulz, Bc.r_ulz);
    const u64 kRlzfsm = pk(A.r_lzfsm, Bc.r_lzfsm);
    const u64 kRlzfpm = pk(A.r_lzfpm, Bc.r_lzfpm);
    const u64 kSfm    = pk(A.sfm, Bc.sfm);
    const u64 kLzsum  = pk(A.lzsum, Bc.lzsum);
    const u64 kUzfwm  = pk(A.uzfwm, Bc.uzfwm);
    const u64 kRlzsum = pk(A.r_lzsum, Bc.r_lzsum);
    const u64 kUzsum  = pk(A.uzsum, Bc.uzsum);
    const u64 kParea  = pk(A.parea, Bc.parea);
    const u64 kFp2    = pk(A.fp2, Bc.fp2);
    const u64 kPbu    = pk(A.pbu, Bc.pbu);
    const u64 kPbuz   = pk(A.pbuz, Bc.pbuz);
    const u64 kCi1    = pk(A.ci1, Bc.ci1);
    const u64 kCgs1   = pk(A.cgs1, Bc.cgs1);
    const u64 kCgp1   = pk(A.cgp1, Bc.cgp1);
    const u64 kC1     = pk(A.c1, Bc.c1);
    const u64 kC2     = pk(A.c2, Bc.c2);
    const u64 kC3     = pk(A.c3, Bc.c3);
    const float rexpA = A.rexp, rexpB = Bc.rexp;

    // packed state
    u64 auztw = pk(0.01f, 0.01f);
    u64 alztw = auztw, uztw = auztw, uzfw = auztw, lztw = auztw;
    u64 lzfs = auztw, lzfp = auztw;
    u64 qs = auztw, qi = auztw, qgs = auztw, qgp = auztw, o1 = auztw;

    const float4* __restrict__ pe4 = (const float4*)p_and_e + tb;  // (p0,e0,p1,e1); row stride B2
    const int nout = T - SAC_WARMUP;
    u64* __restrict__ qout = (u64*)out + tb;                        // row stride B2 (u64 = 2 floats)
    u64* __restrict__ eout = (u64*)(out + (size_t)nout * B) + tb;

    float4 buf[PF];
#pragma unroll
    for (int i = 0; i < PF; i++)
        buf[i] = pe4[(size_t)i * B2];
    const float4* __restrict__ pe_pf = pe4 + (size_t)PF * B2;

    u64 o2 = o1, et = o1;

#define SAC_BODY(cur)                                                              \
    do {                                                                           \
        u64 p  = pk(fmaxf((cur).x, 0.f), fmaxf((cur).z, 0.f));                     \
        u64 e  = pk(fmaxf((cur).y, 0.f), fmaxf((cur).w, 0.f));                     \
        u64 ep    = mul2(kKc, e);                                                  \
        u64 roimp = mul2(kPctim, p);                                               \
        u64 ae2   = mul2(kPctim, ep);                                              \
        u64 ae1   = min2(auztw, mul2(ep, mul2(auztw, kRuztwm)));                   \
        u64 ae3   = relu2(mul2(S2(ep, ae1), mul2(alztw, kRulz)));                  \
        u64 aa    = S2(auztw, ae1);                                                \
        u64 pav   = relu2(add2(S2(p, kUztwm), aa));                                \
        u64 almae3 = S2(alztw, ae3);                                               \
        u64 adsur = relu2(mul2(pav, mul2(almae3, kRlztwm)));                       \
        u64 pam   = add2(S2(pav, adsur), almae3);                                  \
        u64 ars   = relu2(S2(pam, kLztwm));                                        \
        u64 auztw_n = clamp0m(kUztwm, add2(aa, p));                                \
        u64 alztw_n = clamp0m(kLztwm, pam);                                        \
        u64 e1  = min2(uztw, mul2(ep, mul2(uztw, kRuztwm)));                       \
        u64 e2v = clamp0m(uzfw, S2(ep, e1));                                       \
        u64 epe12 = S2(S2(ep, e1), e2v);                                           \
        u64 e3  = relu2(mul2(epe12, mul2(lztw, kRulz)));                           \
        u64 lt1 = relu2(S2(lztw, e3));                                             \
        u64 e4  = mul2(kRiva, ep);                                                 \
        et = add2(add2(add2(ae2, ae1), add2(ae3, e1)), add2(add2(e2v, e3), e4));   \
        u64 uzres = add2(p, S2(add2(uztw, uzfw), add2(e1, e2v)));                  \
        u64 rs = mul2(relu2(S2(uzres, kUzsum)), kParea);                           \
        u64 ut = clamp0m(kUztwm, add2(S2(uztw, e1), p));                           \
        u64 uf = clamp0m(kUzfwm, S2(uzres, ut));                                   \
        u64 ri = mul2(uf, kUzk);                                                   \
        uf = relu2(S2(uf, ri));                                                    \
        u64 gp = S2(kOne, mul2(lzfp, kRlzfpm));                                    \
        u64 gs = S2(kOne, mul2(lzfs, kRlzfsm));                                    \
        u64 coef = min2(mul2(mul2(kFp2, gp), rcp2(add2(gp, gs))), kOne);           \
        u64 lzfsp = add2(lzfs, lzfp);                                              \
        u64 lzdef = add2(lzfsp, lt1);                                              \
        u64 defr  = relu2(S2(kOne, mul2(lzdef, kRlzsum)));                         \
        u64 pw    = pow2x(defr, rexpA, rexpB);                                     \
        u64 perc  = mul2(fma2(kPbuz, pw, kPbu), uf);                               \
        u64 rate  = clamp0m(S2(kLzsum, lzdef), perc);                              \
        uf = relu2(S2(uf, rate));                                                  \
        u64 fx = clamp0m(S2(kSfm, lzfsp),                                          \
                         max2(S2(rate, S2(kLztwm, lt1)), mul2(rate, kPfree)));     \
        u64 perct = S2(rate, fx);                                                  \
        u64 percp = clamp0m(S2(kLzfpm, lzfp),                                      \
                            max2(S2(fx, S2(kLzfsm, lzfs)), mul2(coef, fx)));       \
        u64 percs = relu2(S2(fx, percp));                                          \
        u64 lt = min2(add2(lt1, perct), kLztwm);                                   \
        u64 ls = add2(lzfs, percs);                                                \
        u64 lp = add2(lzfp, percp);                                                \
        u64 rgs = mul2(ls, kLzsk);  ls = relu2(S2(ls, rgs));                       \
        u64 rgp = mul2(lp, kLzpk);  lp = relu2(S2(lp, rgp));                       \
        u64 i1   = add2(add2(qs, qi), add2(qgs, qgp));                             \
        u64 qs_n = add2(add2(roimp, mul2(add2(adsur, ars), kAdimp)), rs);          \
        u64 qi_n = fma2(kCi, qi, mul2(kCi1, ri));                                  \
        u64 qgs_n = fma2(kCgs, qgs, mul2(kCgs1, rgs));                             \
        u64 qgp_n = fma2(kCgp, qgp, mul2(kCgp1, rgp));                             \
        u64 i2   = add2(add2(qs_n, qi_n), add2(qgs_n, qgp_n));                     \
        o2 = fma2(kC1, i1, fma2(kC2, i2, mul2(kC3, o1)));                          \
        auztw = auztw_n; alztw = alztw_n;                                          \
        uztw = ut; uzfw = uf; lztw = lt; lzfs = ls; lzfp = lp;                     \
        qs = qs_n; qi = qi_n; qgs = qgs_n; qgp = qgp_n; o1 = o2;                   \
    } while (0)

    // ---- warmup: no stores, unconditional prefetch ----
#pragma unroll 4
    for (int t = 0; t < SAC_WARMUP; ++t) {
        float4 cur = buf[t & (PF - 1)];
        buf[t & (PF - 1)] = *pe_pf;
        pe_pf += B2;
        SAC_BODY(cur);
    }

    // ---- output phase ----
#pragma unroll 4
    for (int t = SAC_WARMUP; t < T; ++t) {
        float4 cur = buf[t & (PF - 1)];
        if (t + PF < T)
            buf[t & (PF - 1)] = *pe_pf;
        pe_pf += B2;

        SAC_BODY(cur);

        *qout = o2;  qout += B2;   // packed u64 == float2(basinA, basinB)
        *eout = et;  eout += B2;
    }
#undef SAC_BODY
#undef S2
}

extern "C" void kernel_launch(void* const* d_in, const int* in_sizes, int n_in,
                              void* d_out, int out_size)
{
    const float* p_and_e = (const float*)d_in[0];   // [T, B, 2]
    const float* params  = (const float*)d_in[1];   // [B, 21]
    float* out = (float*)d_out;

    int B = in_sizes[1] / 21;
    int T = in_sizes[0] / (2 * B);

    int B2 = B / 2;
    int grid = (B2 + 127) / 128;   // 40 blocks for B=10000 -> 1 warp/SMSP on active SMs
    sac4dpl_pk<<<grid, 128>>>(p_and_e, params, out, T, B);
}

// round 7
// speedup vs baseline: 1.2142x; 1.2142x over previous
#include <cuda_runtime.h>
#include <math.h>

#define SAC_WARMUP 365
#define PF 4

__device__ __forceinline__ float fast_lg2(float x) {
    float r; asm("lg2.approx.f32 %0, %1;" : "=f"(r) : "f"(x)); return r;
}
__device__ __forceinline__ float fast_ex2(float x) {
    float r; asm("ex2.approx.f32 %0, %1;" : "=f"(r) : "f"(x)); return r;
}
// rcp.approx + 1 Newton-Raphson step: ~fp32 precision, off the carry-critical path
__device__ __forceinline__ float fast_rcp(float d) {
    float r; asm("rcp.approx.f32 %0, %1;" : "=f"(r) : "f"(d));
    r = r * (2.0f - d * r);
    return r;
}

__global__ __launch_bounds__(128, 1)
void sac4dpl_kernel(const float* __restrict__ p_and_e,   // [T, B, 2]
                    const float* __restrict__ params,    // [B, 21]
                    float* __restrict__ out,             // [2, T-WARMUP, B]
                    int T, int B)
{
    int b = blockIdx.x * 128 + threadIdx.x;
    if (b >= B) return;

    // ---- load + scale parameters (one-time) ----
    const float lo[21] = {0.1f, 0.0f, 0.0f, 10.0f, 10.0f, 50.0f, 10.0f, 50.0f,
                          0.0f, 0.0f, 0.0f, 5.0f, 1.0f, 0.1f, 0.01f, 0.001f,
                          0.5f, 0.95f, 0.98f, 0.0f, 0.0f};
    const float hi[21] = {1.2f, 0.1f, 0.3f, 100.0f, 100.0f, 400.0f, 100.0f, 1000.0f,
                          0.3f, 0.5f, 0.1f, 350.0f, 4.0f, 0.5f, 0.35f, 0.05f,
                          0.9f, 0.998f, 0.998f, 1.0f, 0.5f};
    float pr[21];
#pragma unroll
    for (int i = 0; i < 21; i++)
        pr[i] = lo[i] + params[(size_t)b * 21 + i] * (hi[i] - lo[i]);

    const float kc    = pr[0],  pctim = pr[1],  adimp = pr[2];
    const float uztwm = pr[3],  uzfwm = pr[4],  lztwm = pr[5];
    const float lzfsm = pr[6],  lzfpm = pr[7];
    const float pfree = pr[9],  riva  = pr[10];
    const float zperc = pr[11], rexp  = pr[12], uzk = pr[13];
    const float lzsk  = pr[14], lzpk  = pr[15];
    const float ci    = pr[16], cgs   = pr[17], cgp = pr[18];
    const float ke    = pr[19], xe    = pr[20];

    // ---- hoisted per-basin constants ----
    const float r_uztwm = 1.0f / uztwm;
    const float r_lztwm = 1.0f / lztwm;
    const float r_ulz   = 1.0f / (uztwm + lztwm);
    const float r_lzfsm = 1.0f / lzfsm;
    const float r_lzfpm = 1.0f / lzfpm;
    const float sfm     = lzfsm + lzfpm;
    const float lzsum   = sfm + lztwm;
    const float r_lzsum = 1.0f / lzsum;
    const float uzsum   = uztwm + uzfwm;
    const float pbase   = lzfsm * lzsk + lzfpm * lzpk;
    const float parea   = 1.0f - pctim - adimp;
    const float fp2     = 2.0f * (lzfpm / sfm);
    const float pbu     = pbase / uzfwm;
    const float pbuz    = pbu * zperc;
    const float ci1     = (1.0f - ci)  * parea;
    const float cgs1    = (1.0f - cgs) * parea;
    const float cgp1    = (1.0f - cgp) * parea;
    const float dt      = 0.5f;
    const float mden    = ke * (1.0f - xe) + dt;
    const float c1      = (ke * xe + dt) / mden;
    const float c2      = (dt - ke * xe) / mden;
    const float c3      = (ke * (1.0f - xe) - dt) / mden;

    // ---- initial carry ----
    float auztw = 0.01f, alztw = 0.01f;
    float uztw  = 0.01f, uzfw  = 0.01f;
    float lztw  = 0.01f, lzfs  = 0.01f, lzfp = 0.01f;
    float qs = 0.01f, qi = 0.01f, qgs = 0.01f, qgp = 0.01f;
    float o1 = 0.01f;
    float o2 = 0.01f, et = 0.01f;

    // pointer-increment addressing
    const float2* __restrict__ pe  = (const float2*)p_and_e + b;
    const int nout = T - SAC_WARMUP;
    float* __restrict__ qout = out + b;
    float* __restrict__ eout = out + (size_t)nout * B + b;

    float2 buf[PF];
#pragma unroll
    for (int i = 0; i < PF; i++)
        buf[i] = pe[(size_t)i * B];
    const float2* __restrict__ pe_pf = pe + (size_t)PF * B;

#define SAC_BODY(cur)                                                          \
    do {                                                                       \
        float p = fmaxf((cur).x, 0.0f);                                        \
        float e = fmaxf((cur).y, 0.0f);                                        \
        float ep    = kc * e;                                                  \
        float roimp = pctim * p;                                               \
        float ae2   = pctim * ep;                                              \
        float ae1    = fminf(auztw, ep * (auztw * r_uztwm));                   \
        float ae3    = fmaxf((ep - ae1) * (alztw * r_ulz), 0.0f);              \
        float pav    = fmaxf(p - (uztwm - (auztw - ae1)), 0.0f);               \
        float almae3 = alztw - ae3;                                            \
        float adsur  = fmaxf(pav * (almae3 * r_lztwm), 0.0f);                  \
        float ars    = fmaxf(pav - adsur + almae3 - lztwm, 0.0f);              \
        float auztw_n = fmaxf(fminf(uztwm, auztw - ae1 + p), 0.0f);            \
        float alztw_n = fmaxf(fminf(lztwm, pav - adsur + almae3), 0.0f);       \
        float e1  = fminf(uztw, ep * (uztw * r_uztwm));                        \
        float e2  = fmaxf(fminf(uzfw, ep - e1), 0.0f);                         \
        float e3  = fmaxf((ep - e1 - e2) * (lztw * r_ulz), 0.0f);              \
        float lt1 = fmaxf(lztw - e3, 0.0f);                                    \
        float e4  = riva * ep;                                                 \
        et = ae2 + ae1 + ae3 + e1 + e2 + e3 + e4;                              \
        float uzres = p + (uztw + uzfw - e1 - e2);                             \
        float rs = fmaxf(uzres - uzsum, 0.0f) * parea;                         \
        float ut = fmaxf(fminf(uztwm, uztw - e1 + p), 0.0f);                   \
        float uf = fmaxf(fminf(uzfwm, uzres - ut), 0.0f);                      \
        float ri = uf * uzk;                                                   \
        uf = fmaxf(uf - ri, 0.0f);                                             \
        float gp = 1.0f - lzfp * r_lzfpm;                                      \
        float gs = 1.0f - lzfs * r_lzfsm;                                      \
        float coef = fminf(fp2 * gp * fast_rcp(gp + gs), 1.0f);                \
        float lzdef = lzfs + lzfp + lt1;                                       \
        float defr  = fmaxf(1.0f - lzdef * r_lzsum, 0.0f);                     \
        float pw    = fast_ex2(rexp * fast_lg2(defr));                         \
        float perc  = (pbu + pbuz * pw) * uf;                                  \
        float rate  = fmaxf(fminf(perc, lzsum - lzdef), 0.0f);                 \
        uf = fmaxf(uf - rate, 0.0f);                                           \
        float fx    = fmaxf(fminf(sfm - (lzfs + lzfp),                         \
                                  fmaxf(rate - (lztwm - lt1), rate * pfree)),  \
                            0.0f);                                             \
        float perct = rate - fx;                                               \
        float percp = fmaxf(fminf(lzfpm - lzfp,                                \
                                  fmaxf(fx - (lzfsm - lzfs), coef * fx)),      \
                            0.0f);                                             \
        float percs = fmaxf(fx - percp, 0.0f);                                 \
        float lt = fminf(lt1 + perct, lztwm);                                  \
        float ls = lzfs + percs;                                               \
        float lp = lzfp + percp;                                               \
        float rgs = ls * lzsk;  ls = fmaxf(ls - rgs, 0.0f);                    \
        float rgp = lp * lzpk;  lp = fmaxf(lp - rgp, 0.0f);                    \
        float i1   = qs + qi + qgs + qgp;                                      \
        float qs_n = roimp + (adsur + ars) * adimp + rs;                       \
        float qi_n = ci  * qi  + ci1  * ri;                                    \
        float qgs_n = cgs * qgs + cgs1 * rgs;                                  \
        float qgp_n = cgp * qgp + cgp1 * rgp;                                  \
        float i2   = qs_n + qi_n + qgs_n + qgp_n;                              \
        o2 = c1 * i1 + c2 * i2 + c3 * o1;                                      \
        auztw = auztw_n; alztw = alztw_n;                                      \
        uztw = ut; uzfw = uf; lztw = lt; lzfs = ls; lzfp = lp;                 \
        qs = qs_n; qi = qi_n; qgs = qgs_n; qgp = qgp_n;                        \
        o1 = o2;                                                               \
    } while (0)

    // ---- phase 1: warmup — no stores, unconditional prefetch ----
#pragma unroll 4
    for (int t = 0; t < SAC_WARMUP; ++t) {
        float2 cur = buf[t & (PF - 1)];
        buf[t & (PF - 1)] = *pe_pf;  pe_pf += B;     // t+PF <= WARMUP-1+PF < T
        SAC_BODY(cur);
    }

    // ---- phase 2: main — unconditional stores AND prefetch ----
#pragma unroll 4
    for (int t = SAC_WARMUP; t < T - PF; ++t) {
        float2 cur = buf[t & (PF - 1)];
        buf[t & (PF - 1)] = *pe_pf;  pe_pf += B;     // t+PF < T guaranteed
        SAC_BODY(cur);
        *qout = o2;  qout += B;
        *eout = et;  eout += B;
    }

    // ---- phase 3: tail — last PF steps, no prefetch ----
#pragma unroll
    for (int t = T - PF; t < T; ++t) {
        float2 cur = buf[t & (PF - 1)];
        SAC_BODY(cur);
        *qout = o2;  qout += B;
        *eout = et;  eout += B;
    }
#undef SAC_BODY
}

extern "C" void kernel_launch(void* const* d_in, const int* in_sizes, int n_in,
                              void* d_out, int out_size)
{
    const float* p_and_e = (const float*)d_in[0];   // [T, B, 2]
    const float* params  = (const float*)d_in[1];   // [B, 21]
    float* out = (float*)d_out;

    int B = in_sizes[1] / 21;
    int T = in_sizes[0] / (2 * B);

    int grid = (B + 127) / 128;   // 79 blocks -> <=1 block/SM, 1 warp/SMSP
    sac4dpl_kernel<<<grid, 128>>>(p_and_e, params, out, T, B);
}

// round 8
// speedup vs baseline: 1.2970x; 1.0682x over previous
#include <cuda_runtime.h>
#include <math.h>

#define SAC_WARMUP 365
#define PF 4

__device__ __forceinline__ float fast_lg2(float x) {
    float r; asm("lg2.approx.f32 %0, %1;" : "=f"(r) : "f"(x)); return r;
}
__device__ __forceinline__ float fast_ex2(float x) {
    float r; asm("ex2.approx.f32 %0, %1;" : "=f"(r) : "f"(x)); return r;
}
// rcp.approx + 1 Newton-Raphson step; off the carry-critical path
__device__ __forceinline__ float fast_rcp(float d) {
    float r; asm("rcp.approx.f32 %0, %1;" : "=f"(r) : "f"(d));
    r = r * (2.0f - d * r);
    return r;
}

// BC > 0: compile-time B (strength-reduced addressing). BC == 0: runtime B.
template <int BC>
__global__ __launch_bounds__(128, 1)
void sac4dpl_kernel(const float* __restrict__ p_and_e,   // [T, B, 2]
                    const float* __restrict__ params,    // [B, 21]
                    float* __restrict__ out,             // [2, T-WARMUP, B]
                    int T, int Brt)
{
    const int B = (BC > 0) ? BC : Brt;
    int b = blockIdx.x * 128 + threadIdx.x;
    if (b >= B) return;

    // ---- load + scale parameters (one-time) ----
    const float lo[21] = {0.1f, 0.0f, 0.0f, 10.0f, 10.0f, 50.0f, 10.0f, 50.0f,
                          0.0f, 0.0f, 0.0f, 5.0f, 1.0f, 0.1f, 0.01f, 0.001f,
                          0.5f, 0.95f, 0.98f, 0.0f, 0.0f};
    const float hi[21] = {1.2f, 0.1f, 0.3f, 100.0f, 100.0f, 400.0f, 100.0f, 1000.0f,
                          0.3f, 0.5f, 0.1f, 350.0f, 4.0f, 0.5f, 0.35f, 0.05f,
                          0.9f, 0.998f, 0.998f, 1.0f, 0.5f};
    float pr[21];
#pragma unroll
    for (int i = 0; i < 21; i++)
        pr[i] = lo[i] + params[(size_t)b * 21 + i] * (hi[i] - lo[i]);

    const float kc    = pr[0],  pctim = pr[1],  adimp = pr[2];
    const float uztwm = pr[3],  uzfwm = pr[4],  lztwm = pr[5];
    const float lzfsm = pr[6],  lzfpm = pr[7];
    const float pfree = pr[9],  riva  = pr[10];
    const float zperc = pr[11], rexp  = pr[12], uzk = pr[13];
    const float lzsk  = pr[14], lzpk  = pr[15];
    const float ci    = pr[16], cgs   = pr[17], cgp = pr[18];
    const float ke    = pr[19], xe    = pr[20];

    // ---- hoisted per-basin constants ----
    const float r_uztwm = 1.0f / uztwm;
    const float r_lztwm = 1.0f / lztwm;
    const float r_ulz   = 1.0f / (uztwm + lztwm);
    const float r_lzfsm = 1.0f / lzfsm;
    const float r_lzfpm = 1.0f / lzfpm;
    const float sfm     = lzfsm + lzfpm;
    const float lzsum   = sfm + lztwm;
    const float r_lzsum = 1.0f / lzsum;
    const float uzsum   = uztwm + uzfwm;
    const float pbase   = lzfsm * lzsk + lzfpm * lzpk;
    const float parea   = 1.0f - pctim - adimp;
    const float fp2     = 2.0f * (lzfpm / sfm);
    const float pbu     = pbase / uzfwm;
    const float pbuz    = pbu * zperc;
    const float ci1     = (1.0f - ci)  * parea;
    const float cgs1    = (1.0f - cgs) * parea;
    const float cgp1    = (1.0f - cgp) * parea;
    const float dt      = 0.5f;
    const float mden    = ke * (1.0f - xe) + dt;
    const float c1      = (ke * xe + dt) / mden;
    const float c2      = (dt - ke * xe) / mden;
    const float c3      = (ke * (1.0f - xe) - dt) / mden;

    // ---- initial carry ----
    float auztw = 0.01f, alztw = 0.01f;
    float uztw  = 0.01f, uzfw  = 0.01f;
    float lztw  = 0.01f, lzfs  = 0.01f, lzfp = 0.01f;
    float qs = 0.01f, qi = 0.01f, qgs = 0.01f, qgp = 0.01f;
    float o1 = 0.01f;
    float o2 = 0.01f, et = 0.01f;

    const float2* __restrict__ pe  = (const float2*)p_and_e + b;
    const int nout = T - SAC_WARMUP;
    float* __restrict__ qout = out + b;
    float* __restrict__ eout = out + (size_t)nout * B + b;

    float2 buf[PF];
#pragma unroll
    for (int i = 0; i < PF; i++)
        buf[i] = pe[(size_t)i * B];
    const float2* __restrict__ pe_pf = pe + (size_t)PF * B;

    // Redundant-clamp-eliminated step. Invariants used (exact up to ~1 ulp,
    // harmless in this contracting system; lg2's domain guard on defr kept):
    //   auztw<=uztwm, uztw<=uztwm, lzfs<=lzfsm, lzfp<=lzfpm, lt<=lztwm,
    //   e1<=ep, ae1<=ep, e2<=uzfw, adsur<=pav, percp<=fx, coef<=1.
#define SAC_BODY(cur)                                                          \
    do {                                                                       \
        float p = fmaxf((cur).x, 0.0f);                                        \
        float e = fmaxf((cur).y, 0.0f);                                        \
        float ep    = kc * e;                                                  \
        float roimp = pctim * p;                                               \
        float ae2   = pctim * ep;                                              \
        float ae1    = fminf(auztw, ep * (auztw * r_uztwm));                   \
        float ae3    = (ep - ae1) * (alztw * r_ulz);                           \
        float pav    = fmaxf(p - (uztwm - (auztw - ae1)), 0.0f);               \
        float almae3 = alztw - ae3;                                            \
        float adsur  = pav * (almae3 * r_lztwm);                               \
        float pam    = pav - adsur + almae3;                                   \
        float ars    = fmaxf(pam - lztwm, 0.0f);                               \
        float auztw_n = fminf(uztwm, auztw - ae1 + p);                         \
        float alztw_n = fminf(lztwm, pam);                                     \
        float e1  = fminf(uztw, ep * (uztw * r_uztwm));                        \
        float e2  = fminf(uzfw, ep - e1);                                      \
        float e3  = (ep - e1 - e2) * (lztw * r_ulz);                           \
        float lt1 = lztw - e3;                                                 \
        float e4  = riva * ep;                                                 \
        et = ae2 + ae1 + ae3 + e1 + e2 + e3 + e4;                              \
        float uzres = p + (uztw + uzfw - e1 - e2);                             \
        float rs = fmaxf(uzres - uzsum, 0.0f) * parea;                         \
        float ut = fminf(uztwm, uztw - e1 + p);                                \
        float uf = fminf(uzfwm, uzres - ut);                                   \
        float ri = uf * uzk;                                                   \
        uf = uf - ri;                                                          \
        float gp = 1.0f - lzfp * r_lzfpm;                                      \
        float gs = 1.0f - lzfs * r_lzfsm;                                      \
        float coef = fminf(fp2 * gp * fast_rcp(gp + gs), 1.0f);                \
        float lzdef = lzfs + lzfp + lt1;                                       \
        float defr  = fmaxf(1.0f - lzdef * r_lzsum, 0.0f);                     \
        float pw    = fast_ex2(rexp * fast_lg2(defr));                         \
        float perc  = (pbu + pbuz * pw) * uf;                                  \
        float rate  = fminf(perc, lzsum - lzdef);                              \
        uf = fmaxf(uf - rate, 0.0f);                                           \
        float fx    = fminf(sfm - (lzfs + lzfp),                               \
                            fmaxf(rate - (lztwm - lt1), rate * pfree));        \
        float perct = rate - fx;                                               \
        float percp = fminf(lzfpm - lzfp,                                      \
                            fmaxf(fx - (lzfsm - lzfs), coef * fx));            \
        float percs = fx - percp;                                              \
        float lt = fminf(lt1 + perct, lztwm);                                  \
        float ls = lzfs + percs;                                               \
        float lp = lzfp + percp;                                               \
        float rgs = ls * lzsk;  ls = ls - rgs;                                 \
        float rgp = lp * lzpk;  lp = lp - rgp;                                 \
        float i1   = qs + qi + qgs + qgp;                                      \
        float qs_n = roimp + (adsur + ars) * adimp + rs;                       \
        float qi_n = ci  * qi  + ci1  * ri;                                    \
        float qgs_n = cgs * qgs + cgs1 * rgs;                                  \
        float qgp_n = cgp * qgp + cgp1 * rgp;                                  \
        float i2   = qs_n + qi_n + qgs_n + qgp_n;                              \
        o2 = c1 * i1 + c2 * i2 + c3 * o1;                                      \
        auztw = auztw_n; alztw = alztw_n;                                      \
        uztw = ut; uzfw = uf; lztw = lt; lzfs = ls; lzfp = lp;                 \
        qs = qs_n; qi = qi_n; qgs = qgs_n; qgp = qgp_n;                        \
        o1 = o2;                                                               \
    } while (0)

    // ---- phase 1: warmup — no stores, unconditional prefetch ----
#pragma unroll 4
    for (int t = 0; t < SAC_WARMUP; ++t) {
        float2 cur = buf[t & (PF - 1)];
        buf[t & (PF - 1)] = *pe_pf;  pe_pf += B;
        SAC_BODY(cur);
    }

    // ---- phase 2: main — unconditional stores AND prefetch ----
#pragma unroll 4
    for (int t = SAC_WARMUP; t < T - PF; ++t) {
        float2 cur = buf[t & (PF - 1)];
        buf[t & (PF - 1)] = *pe_pf;  pe_pf += B;
        SAC_BODY(cur);
        *qout = o2;  qout += B;
        *eout = et;  eout += B;
    }

    // ---- phase 3: tail — last PF steps, no prefetch ----
#pragma unroll
    for (int t = T - PF; t < T; ++t) {
        float2 cur = buf[t & (PF - 1)];
        SAC_BODY(cur);
        *qout = o2;  qout += B;
        *eout = et;  eout += B;
    }
#undef SAC_BODY
}

extern "C" void kernel_launch(void* const* d_in, const int* in_sizes, int n_in,
                              void* d_out, int out_size)
{
    const float* p_and_e = (const float*)d_in[0];   // [T, B, 2]
    const float* params  = (const float*)d_in[1];   // [B, 21]
    float* out = (float*)d_out;

    int B = in_sizes[1] / 21;
    int T = in_sizes[0] / (2 * B);

    int grid = (B + 127) / 128;
    if (B == 10000)
        sac4dpl_kernel<10000><<<grid, 128>>>(p_and_e, params, out, T, B);
    else
        sac4dpl_kernel<0><<<grid, 128>>>(p_and_e, params, out, T, B);
}